// round 14
// baseline (speedup 1.0000x reference)
#include <cuda_runtime.h>
#include <cuda_fp16.h>
#include <cstdint>

#define BDIM 16384
#define DDIM 2048

// ---------------- device scratch ----------------
__device__ __align__(16) __half g_xh   [BDIM * DDIM];
__device__ __align__(16) __half g_wvT  [3][DDIM * DDIM];
__device__ __align__(16) __half g_woh  [3][DDIM * DDIM];
__device__ __align__(16) __half g_Mh   [3][DDIM * DDIM];     // folded weights = [6144, 2048]
__device__ __align__(16) float  g_bfold[3][DDIM];            // = [6144]
__device__ __align__(16) __half g_branch[(size_t)BDIM * 3 * DDIM];   // [B, 6144]  (x + branch)
__device__ __align__(16) __half g_concat[(size_t)BDIM * 3 * DDIM];
__device__ __align__(16) __half g_fw1h [DDIM * 3 * DDIM];
__device__ __align__(16) __half g_fw2h [DDIM * DDIM];
__device__ __align__(16) __half g_ffw1h[4 * DDIM * DDIM];
__device__ __align__(16) __half g_ffw2h[DDIM * 4 * DDIM];
__device__ __align__(16) __half g_h1   [BDIM * DDIM];
__device__ __align__(16) __half g_fused[BDIM * DDIM];
__device__ __align__(16) __half g_h2   [(size_t)BDIM * 4 * DDIM];

// ---------------- helpers ----------------

__device__ __forceinline__ void cvt8(const float* __restrict__ in, __half* __restrict__ out, size_t i8)
{
    const float4* p = (const float4*)in + 2 * i8;
    float4 a = p[0], b = p[1];
    __half2* o = (__half2*)(out + 8 * i8);
    o[0] = __floats2half2_rn(a.x, a.y);
    o[1] = __floats2half2_rn(a.z, a.w);
    o[2] = __floats2half2_rn(b.x, b.y);
    o[3] = __floats2half2_rn(b.z, b.w);
}

// launch 0: per-branch wv transpose->fp16 and wo convert. z = branch.
__global__ void __launch_bounds__(256) prep_branch_w(
    const float* __restrict__ wv0, const float* __restrict__ wv1, const float* __restrict__ wv2,
    const float* __restrict__ wo0, const float* __restrict__ wo1, const float* __restrict__ wo2,
    __half* __restrict__ wvT, __half* __restrict__ woh)
{
    const int z = blockIdx.z;
    const float* wv = (z == 0) ? wv0 : (z == 1) ? wv1 : wv2;
    const float* wo = (z == 0) ? wo0 : (z == 1) ? wo1 : wo2;
    __half* wvTz = wvT + (size_t)z * DDIM * DDIM;
    __half* wohz = woh + (size_t)z * DDIM * DDIM;
    const int bx = blockIdx.x;
    if (bx < 4096) {
        __shared__ float t[32][33];
        const int bxc = (bx & 63) * 32;
        const int byc = (bx >> 6) * 32;
        const int tx = threadIdx.x & 31, ty = threadIdx.x >> 5;  // 32x8
#pragma unroll
        for (int i = 0; i < 4; ++i)
            t[ty + i * 8][tx] = wv[(size_t)(byc + ty + i * 8) * DDIM + bxc + tx];
        __syncthreads();
#pragma unroll
        for (int i = 0; i < 4; ++i)
            wvTz[(size_t)(bxc + ty + i * 8) * DDIM + byc + tx] = __float2half(t[tx][ty + i * 8]);
    } else {
        size_t i = (size_t)(bx - 4096) * 256 + threadIdx.x;   // 524288 chunks
        cvt8(wo, wohz, i);
    }
}

// ---------------- GEMM body (R7 config, best measured) ----------------
#define GBM 128
#define GBN 128
#define GBK 64
#define SST 72
#define STAGE_H (GBM * SST)
#define SMEM_GEMM (4 * STAGE_H * 2)   // 73728 B per CTA; 2 CTAs/SM

#define CPA16(dst, src) asm volatile("cp.async.cg.shared.global [%0], [%1], 16;" :: "r"(dst), "l"(src))

enum { EPI_HB = 0, EPI_HBR = 1, EPI_H = 2, EPI_FINAL = 3, EPI_HBX = 4 };

template<int EPI>
__device__ __forceinline__ void gemm_body(
    const __half* __restrict__ A, const __half* __restrict__ Bm,
    const float* __restrict__ bias,
    const float* __restrict__ addX, const __half* __restrict__ addF,
    void* __restrict__ Cout, int M, int N, int K)
{
    extern __shared__ __align__(16) __half smem[];
    const int tid  = threadIdx.x;
    const int lane = tid & 31;
    const int warp = tid >> 5;
    const int wm = warp >> 2;
    const int wn = warp & 3;
    const int bm0 = blockIdx.y * GBM;
    const int bn0 = blockIdx.x * GBN;

    const int r0 = tid >> 3;
    const int c0 = (tid & 7) << 3;

    const __half* Ag = A + (size_t)(bm0 + r0) * K + c0;
    const __half* Bg = Bm + (size_t)(bn0 + r0) * K + c0;

    const uint32_t sbase = (uint32_t)__cvta_generic_to_shared(smem);
    uint32_t sA[2], sB[2];
#pragma unroll
    for (int s = 0; s < 2; ++s) {
        sA[s] = sbase + (uint32_t)(2 * s)     * STAGE_H * 2;
        sB[s] = sbase + (uint32_t)(2 * s + 1) * STAGE_H * 2;
    }
    const uint32_t so = (uint32_t)(r0 * SST + c0) * 2u;
    const uint32_t sstep = 32u * SST * 2u;

    const int KT = K / GBK;

#pragma unroll
    for (int i = 0; i < 4; ++i) {
        CPA16(sA[0] + so + i * sstep, Ag + (size_t)(32 * i) * K);
        CPA16(sB[0] + so + i * sstep, Bg + (size_t)(32 * i) * K);
    }
    asm volatile("cp.async.commit_group;");

    float acc[4][4][4];
#pragma unroll
    for (int a = 0; a < 4; ++a)
#pragma unroll
        for (int b = 0; b < 4; ++b)
#pragma unroll
            for (int q = 0; q < 4; ++q) acc[a][b][q] = 0.f;

    const int lrow = lane & 15;
    const int lcol = (lane >> 4) << 3;

    const uint32_t aBase = (uint32_t)((wm * 64 + lrow) * SST + lcol) * 2u;
    const uint32_t bBase = (uint32_t)((wn * 32 + lrow) * SST + lcol) * 2u;

    uint32_t af[2][4][4], bf[2][4][2];

#define LDFRAG(cb, sbuf, ksv)                                                              \
    do {                                                                                   \
        const uint32_t kofs = (uint32_t)((ksv) * 16 * 2);                                  \
        _Pragma("unroll")                                                                  \
        for (int mt = 0; mt < 4; ++mt) {                                                   \
            uint32_t addr = sA[sbuf] + aBase + kofs + (uint32_t)(mt * 16 * SST * 2);       \
            asm volatile("ldmatrix.sync.aligned.m8n8.x4.shared.b16 {%0,%1,%2,%3}, [%4];"   \
                         : "=r"(af[cb][mt][0]), "=r"(af[cb][mt][1]),                        \
                           "=r"(af[cb][mt][2]), "=r"(af[cb][mt][3]) : "r"(addr));          \
        }                                                                                  \
        _Pragma("unroll")                                                                  \
        for (int nt2 = 0; nt2 < 2; ++nt2) {                                                \
            uint32_t q0, q1, q2, q3;                                                       \
            uint32_t addr = sB[sbuf] + bBase + kofs + (uint32_t)(nt2 * 16 * SST * 2);      \
            asm volatile("ldmatrix.sync.aligned.m8n8.x4.shared.b16 {%0,%1,%2,%3}, [%4];"   \
                         : "=r"(q0), "=r"(q1), "=r"(q2), "=r"(q3) : "r"(addr));            \
            bf[cb][nt2 * 2 + 0][0] = q0; bf[cb][nt2 * 2 + 0][1] = q2;                      \
            bf[cb][nt2 * 2 + 1][0] = q1; bf[cb][nt2 * 2 + 1][1] = q3;                      \
        }                                                                                  \
    } while (0)

#define MMAS(cb)                                                                           \
    do {                                                                                   \
        _Pragma("unroll")                                                                  \
        for (int mt = 0; mt < 4; ++mt)                                                     \
            _Pragma("unroll")                                                              \
            for (int nt = 0; nt < 4; ++nt)                                                 \
                asm volatile("mma.sync.aligned.m16n8k16.row.col.f32.f16.f16.f32 "          \
                             "{%0,%1,%2,%3}, {%4,%5,%6,%7}, {%8,%9}, {%0,%1,%2,%3};"       \
                             : "+f"(acc[mt][nt][0]), "+f"(acc[mt][nt][1]),                  \
                               "+f"(acc[mt][nt][2]), "+f"(acc[mt][nt][3])                   \
                             : "r"(af[cb][mt][0]), "r"(af[cb][mt][1]),                      \
                               "r"(af[cb][mt][2]), "r"(af[cb][mt][3]),                      \
                               "r"(bf[cb][nt][0]), "r"(bf[cb][nt][1]));                     \
    } while (0)

    int buf = 0;
    for (int kt = 0; kt < KT; ++kt) {
        asm volatile("cp.async.wait_group 0;");
        __syncthreads();
        if (kt + 1 < KT) {
            const int koff = (kt + 1) * GBK;
#pragma unroll
            for (int i = 0; i < 4; ++i) {
                CPA16(sA[buf ^ 1] + so + i * sstep, Ag + koff + (size_t)(32 * i) * K);
                CPA16(sB[buf ^ 1] + so + i * sstep, Bg + koff + (size_t)(32 * i) * K);
            }
            asm volatile("cp.async.commit_group;");
        }
        LDFRAG(0, buf, 0);
        LDFRAG(1, buf, 1);
        MMAS(0);
        LDFRAG(0, buf, 2);
        MMAS(1);
        LDFRAG(1, buf, 3);
        MMAS(0);
        MMAS(1);
        buf ^= 1;
    }

    // epilogue
#pragma unroll
    for (int mt = 0; mt < 4; ++mt) {
        const int mrow = bm0 + wm * 64 + mt * 16 + (lane >> 2);
#pragma unroll
        for (int nt = 0; nt < 4; ++nt) {
            const int ncol = bn0 + wn * 32 + nt * 8 + ((lane & 3) << 1);
            float v0 = acc[mt][nt][0], v1 = acc[mt][nt][1];
            float v2 = acc[mt][nt][2], v3 = acc[mt][nt][3];
            if (EPI != EPI_H) {
                float b0 = bias[ncol], b1 = bias[ncol + 1];
                v0 += b0; v1 += b1; v2 += b0; v3 += b1;
            }
            if (EPI == EPI_HBR) {
                v0 = fmaxf(v0, 0.f); v1 = fmaxf(v1, 0.f);
                v2 = fmaxf(v2, 0.f); v3 = fmaxf(v3, 0.f);
            }
            if (EPI == EPI_HBX) {
                // residual add: x column = ncol mod 2048 (N is a multiple of 2048)
                const int xcol = ncol & (DDIM - 1);
                float2 fa = __half22float2(*(const __half2*)(addF + (size_t)mrow * DDIM + xcol));
                float2 fb = __half22float2(*(const __half2*)(addF + (size_t)(mrow + 8) * DDIM + xcol));
                v0 += fa.x; v1 += fa.y; v2 += fb.x; v3 += fb.y;
            }
            const size_t i0 = (size_t)mrow * N + ncol;
            const size_t i1 = (size_t)(mrow + 8) * N + ncol;
            if (EPI == EPI_FINAL) {
                float* O = (float*)Cout;
                float2 x0 = *(const float2*)(addX + i0);
                float2 x1 = *(const float2*)(addX + i1);
                float2 f0 = __half22float2(*(const __half2*)(addF + i0));
                float2 f1 = __half22float2(*(const __half2*)(addF + i1));
                *(float2*)(O + i0) = make_float2(v0 + x0.x + f0.x, v1 + x0.y + f0.y);
                *(float2*)(O + i1) = make_float2(v2 + x1.x + f1.x, v3 + x1.y + f1.y);
            } else {
                __half* O = (__half*)Cout;
                *(__half2*)(O + i0) = __floats2half2_rn(v0, v1);
                *(__half2*)(O + i1) = __floats2half2_rn(v2, v3);
            }
        }
    }
}

template<int EPI>
__global__ void __launch_bounds__(256, 2)
gemm_nt(const __half* __restrict__ A, const __half* __restrict__ Bm,
        const float* __restrict__ bias,
        const float* __restrict__ addX, const __half* __restrict__ addF,
        void* __restrict__ Cout, int M, int N, int K)
{
    gemm_body<EPI>(A, Bm, bias, addX, addF, Cout, M, N, K);
}

// launch 1: fold GEMM (z<3) + all fp32->fp16 conversions + bias fold (z==3 tail blocks)
#define XCH 4194304u
#define C1 1572864u
#define C2 (C1 + 524288u)
#define C3 (C2 + 2097152u)
#define C4 (C3 + 2097152u)
__global__ void __launch_bounds__(256, 2)
fold_prep_gemm(
    const __half* __restrict__ woh, const __half* __restrict__ wvT, __half* __restrict__ Mh,
    const float* __restrict__ x, __half* __restrict__ xh,
    const float* __restrict__ fw1, __half* __restrict__ fw1h,
    const float* __restrict__ fw2, __half* __restrict__ fw2h,
    const float* __restrict__ ffw1, __half* __restrict__ ffw1h,
    const float* __restrict__ ffw2, __half* __restrict__ ffw2h,
    const float* __restrict__ wo0, const float* __restrict__ wo1, const float* __restrict__ wo2,
    const float* __restrict__ bv0, const float* __restrict__ bv1, const float* __restrict__ bv2,
    const float* __restrict__ bo0, const float* __restrict__ bo1, const float* __restrict__ bo2,
    float* __restrict__ bfold)
{
    const int z = blockIdx.z;
    const size_t DD = (size_t)DDIM * DDIM;
    if (z < 3) {
        gemm_body<EPI_H>(woh + DD * z, wvT + DD * z, nullptr, nullptr, nullptr,
                         (void*)(Mh + DD * z), DDIM, DDIM, DDIM);
        return;
    }
    const uint32_t id = blockIdx.y * 16u + blockIdx.x;   // 0..255
    const uint32_t gt = id * 256u + threadIdx.x;         // 0..65535
    const uint32_t GS = 65536u;

    {
        const int warp = threadIdx.x >> 5, lane = threadIdx.x & 31;
        const int gw = (int)(id * 8u) + warp;            // 0..2047
        const float* wos[3] = {wo0, wo1, wo2};
        const float* bvs[3] = {bv0, bv1, bv2};
        const float* bos[3] = {bo0, bo1, bo2};
#pragma unroll
        for (int zz = 0; zz < 3; ++zz) {
            float s = 0.f;
            const float* wo = wos[zz];
            for (int k = lane; k < DDIM; k += 32) s += bvs[zz][k] * wo[(size_t)gw * DDIM + k];
#pragma unroll
            for (int o = 16; o; o >>= 1) s += __shfl_xor_sync(0xffffffffu, s, o);
            if (lane == 0) bfold[(size_t)zz * DDIM + gw] = s + bos[zz][gw];
        }
    }
    for (uint32_t i = gt; i < XCH; i += GS) cvt8(x, xh, i);
    for (uint32_t i = gt; i < C4; i += GS) {
        if      (i < C1) cvt8(fw1,  fw1h,  i);
        else if (i < C2) cvt8(fw2,  fw2h,  i - C1);
        else if (i < C3) cvt8(ffw1, ffw1h, i - C2);
        else             cvt8(ffw2, ffw2h, i - C3);
    }
}

// launch 3: one-pass fused triple LayerNorm. branch rows already contain x+branch.
// Rows kept packed (3x uint4) to minimize registers.
__global__ void __launch_bounds__(256) ln3_kernel(
    const __half* __restrict__ brc,
    const float* __restrict__ g0, const float* __restrict__ bb0,
    const float* __restrict__ g1, const float* __restrict__ bb1,
    const float* __restrict__ g2, const float* __restrict__ bb2,
    __half* __restrict__ concat)
{
    const int row  = blockIdx.x;
    const int tid  = threadIdx.x;
    const int c    = tid * 8;
    const int warp = tid >> 5, lane = tid & 31;
    __shared__ float red[6][9];

    uint4 br[3];
    float st[6];
#pragma unroll
    for (int j = 0; j < 3; ++j) {
        br[j] = *(const uint4*)(brc + (size_t)row * (3 * DDIM) + (size_t)j * DDIM + c);
        const __half2* bp = (const __half2*)&br[j];
        float sum = 0.f, sq = 0.f;
#pragma unroll
        for (int q = 0; q < 4; ++q) {
            float2 f = __half22float2(bp[q]);
            sum += f.x + f.y;
            sq  += f.x * f.x + f.y * f.y;
        }
        st[2*j] = sum; st[2*j+1] = sq;
    }
#pragma unroll
    for (int o = 16; o; o >>= 1) {
#pragma unroll
        for (int q = 0; q < 6; ++q) st[q] += __shfl_xor_sync(0xffffffffu, st[q], o);
    }
    if (lane == 0) {
#pragma unroll
        for (int q = 0; q < 6; ++q) red[q][warp] = st[q];
    }
    __syncthreads();
    if (tid < 6) {
        float a = 0.f;
#pragma unroll
        for (int i = 0; i < 8; ++i) a += red[tid][i];
        red[tid][8] = a;
    }
    __syncthreads();

    const float* gs[3] = {g0, g1, g2};
    const float* bs[3] = {bb0, bb1, bb2};
#pragma unroll
    for (int j = 0; j < 3; ++j) {
        const float mean = red[2*j][8] * (1.0f / DDIM);
        const float var  = red[2*j+1][8] * (1.0f / DDIM) - mean * mean;
        const float inv  = rsqrtf(var + 1e-5f);
        float4 gA = *(const float4*)(gs[j] + c);
        float4 gB = *(const float4*)(gs[j] + c + 4);
        float4 bA = *(const float4*)(bs[j] + c);
        float4 bB = *(const float4*)(bs[j] + c + 4);
        float gg[8]  = {gA.x, gA.y, gA.z, gA.w, gB.x, gB.y, gB.z, gB.w};
        float bbv[8] = {bA.x, bA.y, bA.z, bA.w, bB.x, bB.y, bB.z, bB.w};
        const __half2* bp = (const __half2*)&br[j];
        uint4 outw;
        __half2* ow = (__half2*)&outw;
#pragma unroll
        for (int q = 0; q < 4; ++q) {
            float2 f = __half22float2(bp[q]);
            ow[q] = __floats2half2_rn((f.x - mean) * inv * gg[2*q]   + bbv[2*q],
                                      (f.y - mean) * inv * gg[2*q+1] + bbv[2*q+1]);
        }
        *(uint4*)(concat + (size_t)row * (3 * DDIM) + (size_t)j * DDIM + c) = outw;
    }
}

// ---------------- launcher ----------------
extern "C" void kernel_launch(void* const* d_in, const int* in_sizes, int n_in,
                              void* d_out, int out_size)
{
    (void)in_sizes; (void)n_in; (void)out_size;
    const float* x     = (const float*)d_in[0];
    const float* wv[3] = {(const float*)d_in[1], (const float*)d_in[5], (const float*)d_in[9]};
    const float* bv[3] = {(const float*)d_in[2], (const float*)d_in[6], (const float*)d_in[10]};
    const float* wo[3] = {(const float*)d_in[3], (const float*)d_in[7], (const float*)d_in[11]};
    const float* bo[3] = {(const float*)d_in[4], (const float*)d_in[8], (const float*)d_in[12]};
    const float* g[3]  = {(const float*)d_in[13], (const float*)d_in[15], (const float*)d_in[17]};
    const float* bb[3] = {(const float*)d_in[14], (const float*)d_in[16], (const float*)d_in[18]};
    const float* fw1  = (const float*)d_in[19]; const float* fb1  = (const float*)d_in[20];
    const float* fw2  = (const float*)d_in[21]; const float* fb2  = (const float*)d_in[22];
    const float* ffw1 = (const float*)d_in[23]; const float* ffb1 = (const float*)d_in[24];
    const float* ffw2 = (const float*)d_in[25]; const float* ffb2 = (const float*)d_in[26];

    void *p;
    __half *xh, *wvT, *woh, *Mh, *branch, *concat, *fw1h, *fw2h, *ffw1h, *ffw2h, *h1, *fused, *h2;
    float *bfold;
    cudaGetSymbolAddress(&p, g_xh);     xh     = (__half*)p;
    cudaGetSymbolAddress(&p, g_wvT);    wvT    = (__half*)p;
    cudaGetSymbolAddress(&p, g_woh);    woh    = (__half*)p;
    cudaGetSymbolAddress(&p, g_Mh);     Mh     = (__half*)p;
    cudaGetSymbolAddress(&p, g_bfold);  bfold  = (float*)p;
    cudaGetSymbolAddress(&p, g_branch); branch = (__half*)p;
    cudaGetSymbolAddress(&p, g_concat); concat = (__half*)p;
    cudaGetSymbolAddress(&p, g_fw1h);   fw1h   = (__half*)p;
    cudaGetSymbolAddress(&p, g_fw2h);   fw2h   = (__half*)p;
    cudaGetSymbolAddress(&p, g_ffw1h);  ffw1h  = (__half*)p;
    cudaGetSymbolAddress(&p, g_ffw2h);  ffw2h  = (__half*)p;
    cudaGetSymbolAddress(&p, g_h1);     h1     = (__half*)p;
    cudaGetSymbolAddress(&p, g_fused);  fused  = (__half*)p;
    cudaGetSymbolAddress(&p, g_h2);     h2     = (__half*)p;

    cudaFuncSetAttribute(gemm_nt<EPI_HB>,    cudaFuncAttributeMaxDynamicSharedMemorySize, SMEM_GEMM);
    cudaFuncSetAttribute(gemm_nt<EPI_HBR>,   cudaFuncAttributeMaxDynamicSharedMemorySize, SMEM_GEMM);
    cudaFuncSetAttribute(gemm_nt<EPI_HBX>,   cudaFuncAttributeMaxDynamicSharedMemorySize, SMEM_GEMM);
    cudaFuncSetAttribute(gemm_nt<EPI_FINAL>, cudaFuncAttributeMaxDynamicSharedMemorySize, SMEM_GEMM);
    cudaFuncSetAttribute(fold_prep_gemm,     cudaFuncAttributeMaxDynamicSharedMemorySize, SMEM_GEMM);

    const int D  = DDIM;
    const int Bn = BDIM;

    // launch 0: branch weight transpose + wo convert
    prep_branch_w<<<dim3(4096 + 2048, 1, 3), 256>>>(
        wv[0], wv[1], wv[2], wo[0], wo[1], wo[2], wvT, woh);
    // launch 1: fold GEMM (z<3) + all conversions + bias fold (z==3)
    fold_prep_gemm<<<dim3(16, 16, 4), 256, SMEM_GEMM>>>(
        woh, wvT, Mh,
        x, xh, fw1, fw1h, fw2, fw2h, ffw1, ffw1h, ffw2, ffw2h,
        wo[0], wo[1], wo[2], bv[0], bv[1], bv[2], bo[0], bo[1], bo[2], bfold);
    // launch 2: merged branch GEMM [B,6144] with fused x-residual
    gemm_nt<EPI_HBX><<<dim3(3 * D / GBN, Bn / GBM), 256, SMEM_GEMM>>>(
        xh, Mh, bfold, nullptr, xh, (void*)branch, Bn, 3 * D, D);
    // launch 3 (ncu capture slot): fused triple LayerNorm -> concat
    ln3_kernel<<<Bn, 256>>>(branch, g[0], bb[0], g[1], bb[1], g[2], bb[2], concat);
    // launch 4: h1 = relu(concat @ fw1^T + fb1)
    gemm_nt<EPI_HBR><<<dim3(D / GBN, Bn / GBM), 256, SMEM_GEMM>>>(
        concat, fw1h, fb1, nullptr, nullptr, (void*)h1, Bn, D, 3 * D);
    // launch 5: fused = h1 @ fw2^T + fb2
    gemm_nt<EPI_HB><<<dim3(D / GBN, Bn / GBM), 256, SMEM_GEMM>>>(
        h1, fw2h, fb2, nullptr, nullptr, (void*)fused, Bn, D, D);
    // launch 6: h2 = relu(fused @ ffw1^T + ffb1)
    gemm_nt<EPI_HBR><<<dim3(4 * D / GBN, Bn / GBM), 256, SMEM_GEMM>>>(
        fused, ffw1h, ffb1, nullptr, nullptr, (void*)h2, Bn, 4 * D, D);
    // launch 7: out = x + fused + (h2 @ ffw2^T + ffb2)
    gemm_nt<EPI_FINAL><<<dim3(D / GBN, Bn / GBM), 256, SMEM_GEMM>>>(
        h2, ffw2h, ffb2, x, fused, d_out, Bn, D, 4 * D);
}

// round 15
// speedup vs baseline: 1.0032x; 1.0032x over previous
#include <cuda_runtime.h>
#include <cuda_fp16.h>
#include <cstdint>

#define BDIM 16384
#define DDIM 2048

// ---------------- device scratch ----------------
__device__ __align__(16) __half g_xh   [BDIM * DDIM];
__device__ __align__(16) __half g_wvT  [3][DDIM * DDIM];
__device__ __align__(16) __half g_woh  [3][DDIM * DDIM];
__device__ __align__(16) __half g_Mh   [3][DDIM * DDIM];     // folded weights = [6144, 2048]
__device__ __align__(16) float  g_bfold[3][DDIM];            // = [6144]
__device__ __align__(16) __half g_gbh  [6][DDIM];            // packed fp16 {g0,b0,g1,b1,g2,b2}
__device__ __align__(16) __half g_branch[(size_t)BDIM * 3 * DDIM];   // [B, 6144]
__device__ __align__(16) __half g_concat[(size_t)BDIM * 3 * DDIM];
__device__ __align__(16) __half g_fw1h [DDIM * 3 * DDIM];
__device__ __align__(16) __half g_fw2h [DDIM * DDIM];
__device__ __align__(16) __half g_ffw1h[4 * DDIM * DDIM];
__device__ __align__(16) __half g_ffw2h[DDIM * 4 * DDIM];
__device__ __align__(16) __half g_h1   [BDIM * DDIM];
__device__ __align__(16) __half g_fused[BDIM * DDIM];
__device__ __align__(16) __half g_h2   [(size_t)BDIM * 4 * DDIM];

// ---------------- helpers ----------------

__device__ __forceinline__ void cvt8(const float* __restrict__ in, __half* __restrict__ out, size_t i8)
{
    const float4* p = (const float4*)in + 2 * i8;
    float4 a = p[0], b = p[1];
    __half2* o = (__half2*)(out + 8 * i8);
    o[0] = __floats2half2_rn(a.x, a.y);
    o[1] = __floats2half2_rn(a.z, a.w);
    o[2] = __floats2half2_rn(b.x, b.y);
    o[3] = __floats2half2_rn(b.z, b.w);
}

// launch 0: per-branch wv transpose->fp16 and wo convert. z = branch.
__global__ void __launch_bounds__(256) prep_branch_w(
    const float* __restrict__ wv0, const float* __restrict__ wv1, const float* __restrict__ wv2,
    const float* __restrict__ wo0, const float* __restrict__ wo1, const float* __restrict__ wo2,
    __half* __restrict__ wvT, __half* __restrict__ woh)
{
    const int z = blockIdx.z;
    const float* wv = (z == 0) ? wv0 : (z == 1) ? wv1 : wv2;
    const float* wo = (z == 0) ? wo0 : (z == 1) ? wo1 : wo2;
    __half* wvTz = wvT + (size_t)z * DDIM * DDIM;
    __half* wohz = woh + (size_t)z * DDIM * DDIM;
    const int bx = blockIdx.x;
    if (bx < 4096) {
        __shared__ float t[32][33];
        const int bxc = (bx & 63) * 32;
        const int byc = (bx >> 6) * 32;
        const int tx = threadIdx.x & 31, ty = threadIdx.x >> 5;  // 32x8
#pragma unroll
        for (int i = 0; i < 4; ++i)
            t[ty + i * 8][tx] = wv[(size_t)(byc + ty + i * 8) * DDIM + bxc + tx];
        __syncthreads();
#pragma unroll
        for (int i = 0; i < 4; ++i)
            wvTz[(size_t)(bxc + ty + i * 8) * DDIM + byc + tx] = __float2half(t[tx][ty + i * 8]);
    } else {
        size_t i = (size_t)(bx - 4096) * 256 + threadIdx.x;   // 524288 chunks
        cvt8(wo, wohz, i);
    }
}

// ---------------- GEMM body (R7 config, best measured) ----------------
#define GBM 128
#define GBN 128
#define GBK 64
#define SST 72
#define STAGE_H (GBM * SST)
#define SMEM_GEMM (4 * STAGE_H * 2)   // 73728 B per CTA; 2 CTAs/SM

#define CPA16(dst, src) asm volatile("cp.async.cg.shared.global [%0], [%1], 16;" :: "r"(dst), "l"(src))

enum { EPI_HB = 0, EPI_HBR = 1, EPI_H = 2, EPI_FINAL = 3 };

template<int EPI>
__device__ __forceinline__ void gemm_body(
    const __half* __restrict__ A, const __half* __restrict__ Bm,
    const float* __restrict__ bias,
    const float* __restrict__ addX, const __half* __restrict__ addF,
    void* __restrict__ Cout, int M, int N, int K)
{
    extern __shared__ __align__(16) __half smem[];
    const int tid  = threadIdx.x;
    const int lane = tid & 31;
    const int warp = tid >> 5;
    const int wm = warp >> 2;
    const int wn = warp & 3;
    const int bm0 = blockIdx.y * GBM;
    const int bn0 = blockIdx.x * GBN;

    const int r0 = tid >> 3;
    const int c0 = (tid & 7) << 3;

    const __half* Ag = A + (size_t)(bm0 + r0) * K + c0;
    const __half* Bg = Bm + (size_t)(bn0 + r0) * K + c0;

    const uint32_t sbase = (uint32_t)__cvta_generic_to_shared(smem);
    uint32_t sA[2], sB[2];
#pragma unroll
    for (int s = 0; s < 2; ++s) {
        sA[s] = sbase + (uint32_t)(2 * s)     * STAGE_H * 2;
        sB[s] = sbase + (uint32_t)(2 * s + 1) * STAGE_H * 2;
    }
    const uint32_t so = (uint32_t)(r0 * SST + c0) * 2u;
    const uint32_t sstep = 32u * SST * 2u;

    const int KT = K / GBK;

#pragma unroll
    for (int i = 0; i < 4; ++i) {
        CPA16(sA[0] + so + i * sstep, Ag + (size_t)(32 * i) * K);
        CPA16(sB[0] + so + i * sstep, Bg + (size_t)(32 * i) * K);
    }
    asm volatile("cp.async.commit_group;");

    float acc[4][4][4];
#pragma unroll
    for (int a = 0; a < 4; ++a)
#pragma unroll
        for (int b = 0; b < 4; ++b)
#pragma unroll
            for (int q = 0; q < 4; ++q) acc[a][b][q] = 0.f;

    const int lrow = lane & 15;
    const int lcol = (lane >> 4) << 3;

    const uint32_t aBase = (uint32_t)((wm * 64 + lrow) * SST + lcol) * 2u;
    const uint32_t bBase = (uint32_t)((wn * 32 + lrow) * SST + lcol) * 2u;

    uint32_t af[2][4][4], bf[2][4][2];

#define LDFRAG(cb, sbuf, ksv)                                                              \
    do {                                                                                   \
        const uint32_t kofs = (uint32_t)((ksv) * 16 * 2);                                  \
        _Pragma("unroll")                                                                  \
        for (int mt = 0; mt < 4; ++mt) {                                                   \
            uint32_t addr = sA[sbuf] + aBase + kofs + (uint32_t)(mt * 16 * SST * 2);       \
            asm volatile("ldmatrix.sync.aligned.m8n8.x4.shared.b16 {%0,%1,%2,%3}, [%4];"   \
                         : "=r"(af[cb][mt][0]), "=r"(af[cb][mt][1]),                        \
                           "=r"(af[cb][mt][2]), "=r"(af[cb][mt][3]) : "r"(addr));          \
        }                                                                                  \
        _Pragma("unroll")                                                                  \
        for (int nt2 = 0; nt2 < 2; ++nt2) {                                                \
            uint32_t q0, q1, q2, q3;                                                       \
            uint32_t addr = sB[sbuf] + bBase + kofs + (uint32_t)(nt2 * 16 * SST * 2);      \
            asm volatile("ldmatrix.sync.aligned.m8n8.x4.shared.b16 {%0,%1,%2,%3}, [%4];"   \
                         : "=r"(q0), "=r"(q1), "=r"(q2), "=r"(q3) : "r"(addr));            \
            bf[cb][nt2 * 2 + 0][0] = q0; bf[cb][nt2 * 2 + 0][1] = q2;                      \
            bf[cb][nt2 * 2 + 1][0] = q1; bf[cb][nt2 * 2 + 1][1] = q3;                      \
        }                                                                                  \
    } while (0)

#define MMAS(cb)                                                                           \
    do {                                                                                   \
        _Pragma("unroll")                                                                  \
        for (int mt = 0; mt < 4; ++mt)                                                     \
            _Pragma("unroll")                                                              \
            for (int nt = 0; nt < 4; ++nt)                                                 \
                asm volatile("mma.sync.aligned.m16n8k16.row.col.f32.f16.f16.f32 "          \
                             "{%0,%1,%2,%3}, {%4,%5,%6,%7}, {%8,%9}, {%0,%1,%2,%3};"       \
                             : "+f"(acc[mt][nt][0]), "+f"(acc[mt][nt][1]),                  \
                               "+f"(acc[mt][nt][2]), "+f"(acc[mt][nt][3])                   \
                             : "r"(af[cb][mt][0]), "r"(af[cb][mt][1]),                      \
                               "r"(af[cb][mt][2]), "r"(af[cb][mt][3]),                      \
                               "r"(bf[cb][nt][0]), "r"(bf[cb][nt][1]));                     \
    } while (0)

    int buf = 0;
    for (int kt = 0; kt < KT; ++kt) {
        asm volatile("cp.async.wait_group 0;");
        __syncthreads();
        if (kt + 1 < KT) {
            const int koff = (kt + 1) * GBK;
#pragma unroll
            for (int i = 0; i < 4; ++i) {
                CPA16(sA[buf ^ 1] + so + i * sstep, Ag + koff + (size_t)(32 * i) * K);
                CPA16(sB[buf ^ 1] + so + i * sstep, Bg + koff + (size_t)(32 * i) * K);
            }
            asm volatile("cp.async.commit_group;");
        }
        LDFRAG(0, buf, 0);
        LDFRAG(1, buf, 1);
        MMAS(0);
        LDFRAG(0, buf, 2);
        MMAS(1);
        LDFRAG(1, buf, 3);
        MMAS(0);
        MMAS(1);
        buf ^= 1;
    }

    // epilogue
#pragma unroll
    for (int mt = 0; mt < 4; ++mt) {
        const int mrow = bm0 + wm * 64 + mt * 16 + (lane >> 2);
#pragma unroll
        for (int nt = 0; nt < 4; ++nt) {
            const int ncol = bn0 + wn * 32 + nt * 8 + ((lane & 3) << 1);
            float v0 = acc[mt][nt][0], v1 = acc[mt][nt][1];
            float v2 = acc[mt][nt][2], v3 = acc[mt][nt][3];
            if (EPI != EPI_H) {
                float b0 = bias[ncol], b1 = bias[ncol + 1];
                v0 += b0; v1 += b1; v2 += b0; v3 += b1;
            }
            if (EPI == EPI_HBR) {
                v0 = fmaxf(v0, 0.f); v1 = fmaxf(v1, 0.f);
                v2 = fmaxf(v2, 0.f); v3 = fmaxf(v3, 0.f);
            }
            const size_t i0 = (size_t)mrow * N + ncol;
            const size_t i1 = (size_t)(mrow + 8) * N + ncol;
            if (EPI == EPI_FINAL) {
                float* O = (float*)Cout;
                float2 x0 = *(const float2*)(addX + i0);
                float2 x1 = *(const float2*)(addX + i1);
                float2 f0 = __half22float2(*(const __half2*)(addF + i0));
                float2 f1 = __half22float2(*(const __half2*)(addF + i1));
                *(float2*)(O + i0) = make_float2(v0 + x0.x + f0.x, v1 + x0.y + f0.y);
                *(float2*)(O + i1) = make_float2(v2 + x1.x + f1.x, v3 + x1.y + f1.y);
            } else {
                __half* O = (__half*)Cout;
                *(__half2*)(O + i0) = __floats2half2_rn(v0, v1);
                *(__half2*)(O + i1) = __floats2half2_rn(v2, v3);
            }
        }
    }
}

template<int EPI>
__global__ void __launch_bounds__(256, 2)
gemm_nt(const __half* __restrict__ A, const __half* __restrict__ Bm,
        const float* __restrict__ bias,
        const float* __restrict__ addX, const __half* __restrict__ addF,
        void* __restrict__ Cout, int M, int N, int K)
{
    gemm_body<EPI>(A, Bm, bias, addX, addF, Cout, M, N, K);
}

// launch 1: fold GEMM (z<3) + conversions + bias fold + gamma/beta pack (z==3)
#define XCH 4194304u
#define C1 1572864u
#define C2 (C1 + 524288u)
#define C3 (C2 + 2097152u)
#define C4 (C3 + 2097152u)
__global__ void __launch_bounds__(256, 2)
fold_prep_gemm(
    const __half* __restrict__ woh, const __half* __restrict__ wvT, __half* __restrict__ Mh,
    const float* __restrict__ x, __half* __restrict__ xh,
    const float* __restrict__ fw1, __half* __restrict__ fw1h,
    const float* __restrict__ fw2, __half* __restrict__ fw2h,
    const float* __restrict__ ffw1, __half* __restrict__ ffw1h,
    const float* __restrict__ ffw2, __half* __restrict__ ffw2h,
    const float* __restrict__ wo0, const float* __restrict__ wo1, const float* __restrict__ wo2,
    const float* __restrict__ bv0, const float* __restrict__ bv1, const float* __restrict__ bv2,
    const float* __restrict__ bo0, const float* __restrict__ bo1, const float* __restrict__ bo2,
    float* __restrict__ bfold,
    const float* __restrict__ g0, const float* __restrict__ bb0,
    const float* __restrict__ g1, const float* __restrict__ bb1,
    const float* __restrict__ g2, const float* __restrict__ bb2,
    __half* __restrict__ gbh)
{
    const int z = blockIdx.z;
    const size_t DD = (size_t)DDIM * DDIM;
    if (z < 3) {
        gemm_body<EPI_H>(woh + DD * z, wvT + DD * z, nullptr, nullptr, nullptr,
                         (void*)(Mh + DD * z), DDIM, DDIM, DDIM);
        return;
    }
    const uint32_t id = blockIdx.y * 16u + blockIdx.x;   // 0..255
    const uint32_t gt = id * 256u + threadIdx.x;         // 0..65535
    const uint32_t GS = 65536u;

    // fold bias: warp per row, 3 branches
    {
        const int warp = threadIdx.x >> 5, lane = threadIdx.x & 31;
        const int gw = (int)(id * 8u) + warp;            // 0..2047
        const float* wos[3] = {wo0, wo1, wo2};
        const float* bvs[3] = {bv0, bv1, bv2};
        const float* bos[3] = {bo0, bo1, bo2};
#pragma unroll
        for (int zz = 0; zz < 3; ++zz) {
            float s = 0.f;
            const float* wo = wos[zz];
            for (int k = lane; k < DDIM; k += 32) s += bvs[zz][k] * wo[(size_t)gw * DDIM + k];
#pragma unroll
            for (int o = 16; o; o >>= 1) s += __shfl_xor_sync(0xffffffffu, s, o);
            if (lane == 0) bfold[(size_t)zz * DDIM + gw] = s + bos[zz][gw];
        }
    }
    // pack gamma/beta to fp16: 6 arrays x 256 chunks = 1536 chunks
    if (gt < 1536u) {
        const float* srcs[6] = {g0, bb0, g1, bb1, g2, bb2};
        const uint32_t which = gt >> 8;
        cvt8(srcs[which], gbh + (size_t)which * DDIM, gt & 255u);
    }
    for (uint32_t i = gt; i < XCH; i += GS) cvt8(x, xh, i);
    for (uint32_t i = gt; i < C4; i += GS) {
        if      (i < C1) cvt8(fw1,  fw1h,  i);
        else if (i < C2) cvt8(fw2,  fw2h,  i - C1);
        else if (i < C3) cvt8(ffw1, ffw1h, i - C2);
        else             cvt8(ffw2, ffw2h, i - C3);
    }
}

// launch 3: one-pass fused triple LayerNorm, 16B-vectorized, fp16 gamma/beta.
__global__ void __launch_bounds__(256) ln3_kernel(
    const __half* __restrict__ xh,
    const __half* __restrict__ brc,
    const __half* __restrict__ gbh,
    __half* __restrict__ concat)
{
    const int row  = blockIdx.x;
    const int tid  = threadIdx.x;
    const int c    = tid * 8;
    const int warp = tid >> 5, lane = tid & 31;
    __shared__ float red[6][9];

    float xv[8];
    {
        uint4 xr = *(const uint4*)(xh + (size_t)row * DDIM + c);
        const __half2* xp = (const __half2*)&xr;
#pragma unroll
        for (int q = 0; q < 4; ++q) {
            float2 f = __half22float2(xp[q]);
            xv[2*q] = f.x; xv[2*q+1] = f.y;
        }
    }

    float s[3][8];
    float st[6];
#pragma unroll
    for (int j = 0; j < 3; ++j) {
        uint4 br = *(const uint4*)(brc + (size_t)row * (3 * DDIM) + (size_t)j * DDIM + c);
        const __half2* bp = (const __half2*)&br;
        float sum = 0.f, sq = 0.f;
#pragma unroll
        for (int q = 0; q < 4; ++q) {
            float2 f = __half22float2(bp[q]);
            float a0 = xv[2*q]   + f.x;
            float a1 = xv[2*q+1] + f.y;
            s[j][2*q] = a0; s[j][2*q+1] = a1;
            sum += a0 + a1;
            sq  += a0 * a0 + a1 * a1;
        }
        st[2*j] = sum; st[2*j+1] = sq;
    }
#pragma unroll
    for (int o = 16; o; o >>= 1) {
#pragma unroll
        for (int q = 0; q < 6; ++q) st[q] += __shfl_xor_sync(0xffffffffu, st[q], o);
    }
    if (lane == 0) {
#pragma unroll
        for (int q = 0; q < 6; ++q) red[q][warp] = st[q];
    }
    __syncthreads();
    if (tid < 6) {
        float a = 0.f;
#pragma unroll
        for (int i = 0; i < 8; ++i) a += red[tid][i];
        red[tid][8] = a;
    }
    __syncthreads();

#pragma unroll
    for (int j = 0; j < 3; ++j) {
        const float mean = red[2*j][8] * (1.0f / DDIM);
        const float var  = red[2*j+1][8] * (1.0f / DDIM) - mean * mean;
        const float inv  = rsqrtf(var + 1e-5f);
        uint4 gw4 = *(const uint4*)(gbh + (size_t)(2*j)     * DDIM + c);
        uint4 bw4 = *(const uint4*)(gbh + (size_t)(2*j + 1) * DDIM + c);
        const __half2* gp  = (const __half2*)&gw4;
        const __half2* bp2 = (const __half2*)&bw4;
        uint4 outw;
        __half2* ow = (__half2*)&outw;
#pragma unroll
        for (int q = 0; q < 4; ++q) {
            float2 gf = __half22float2(gp[q]);
            float2 bf = __half22float2(bp2[q]);
            ow[q] = __floats2half2_rn((s[j][2*q]   - mean) * inv * gf.x + bf.x,
                                      (s[j][2*q+1] - mean) * inv * gf.y + bf.y);
        }
        *(uint4*)(concat + (size_t)row * (3 * DDIM) + (size_t)j * DDIM + c) = outw;
    }
}

// ---------------- launcher ----------------
extern "C" void kernel_launch(void* const* d_in, const int* in_sizes, int n_in,
                              void* d_out, int out_size)
{
    (void)in_sizes; (void)n_in; (void)out_size;
    const float* x     = (const float*)d_in[0];
    const float* wv[3] = {(const float*)d_in[1], (const float*)d_in[5], (const float*)d_in[9]};
    const float* bv[3] = {(const float*)d_in[2], (const float*)d_in[6], (const float*)d_in[10]};
    const float* wo[3] = {(const float*)d_in[3], (const float*)d_in[7], (const float*)d_in[11]};
    const float* bo[3] = {(const float*)d_in[4], (const float*)d_in[8], (const float*)d_in[12]};
    const float* g[3]  = {(const float*)d_in[13], (const float*)d_in[15], (const float*)d_in[17]};
    const float* bb[3] = {(const float*)d_in[14], (const float*)d_in[16], (const float*)d_in[18]};
    const float* fw1  = (const float*)d_in[19]; const float* fb1  = (const float*)d_in[20];
    const float* fw2  = (const float*)d_in[21]; const float* fb2  = (const float*)d_in[22];
    const float* ffw1 = (const float*)d_in[23]; const float* ffb1 = (const float*)d_in[24];
    const float* ffw2 = (const float*)d_in[25]; const float* ffb2 = (const float*)d_in[26];

    void *p;
    __half *xh, *wvT, *woh, *Mh, *branch, *concat, *fw1h, *fw2h, *ffw1h, *ffw2h, *h1, *fused, *h2, *gbh;
    float *bfold;
    cudaGetSymbolAddress(&p, g_xh);     xh     = (__half*)p;
    cudaGetSymbolAddress(&p, g_wvT);    wvT    = (__half*)p;
    cudaGetSymbolAddress(&p, g_woh);    woh    = (__half*)p;
    cudaGetSymbolAddress(&p, g_Mh);     Mh     = (__half*)p;
    cudaGetSymbolAddress(&p, g_bfold);  bfold  = (float*)p;
    cudaGetSymbolAddress(&p, g_gbh);    gbh    = (__half*)p;
    cudaGetSymbolAddress(&p, g_branch); branch = (__half*)p;
    cudaGetSymbolAddress(&p, g_concat); concat = (__half*)p;
    cudaGetSymbolAddress(&p, g_fw1h);   fw1h   = (__half*)p;
    cudaGetSymbolAddress(&p, g_fw2h);   fw2h   = (__half*)p;
    cudaGetSymbolAddress(&p, g_ffw1h);  ffw1h  = (__half*)p;
    cudaGetSymbolAddress(&p, g_ffw2h);  ffw2h  = (__half*)p;
    cudaGetSymbolAddress(&p, g_h1);     h1     = (__half*)p;
    cudaGetSymbolAddress(&p, g_fused);  fused  = (__half*)p;
    cudaGetSymbolAddress(&p, g_h2);     h2     = (__half*)p;

    cudaFuncSetAttribute(gemm_nt<EPI_HB>,    cudaFuncAttributeMaxDynamicSharedMemorySize, SMEM_GEMM);
    cudaFuncSetAttribute(gemm_nt<EPI_HBR>,   cudaFuncAttributeMaxDynamicSharedMemorySize, SMEM_GEMM);
    cudaFuncSetAttribute(gemm_nt<EPI_FINAL>, cudaFuncAttributeMaxDynamicSharedMemorySize, SMEM_GEMM);
    cudaFuncSetAttribute(fold_prep_gemm,     cudaFuncAttributeMaxDynamicSharedMemorySize, SMEM_GEMM);

    const int D  = DDIM;
    const int Bn = BDIM;

    // launch 0: branch weight transpose + wo convert
    prep_branch_w<<<dim3(4096 + 2048, 1, 3), 256>>>(
        wv[0], wv[1], wv[2], wo[0], wo[1], wo[2], wvT, woh);
    // launch 1: fold GEMM (z<3) + conversions + bias fold + gamma/beta pack (z==3)
    fold_prep_gemm<<<dim3(16, 16, 4), 256, SMEM_GEMM>>>(
        woh, wvT, Mh,
        x, xh, fw1, fw1h, fw2, fw2h, ffw1, ffw1h, ffw2, ffw2h,
        wo[0], wo[1], wo[2], bv[0], bv[1], bv[2], bo[0], bo[1], bo[2], bfold,
        g[0], bb[0], g[1], bb[1], g[2], bb[2], gbh);
    // launch 2: merged branch GEMM [B,6144]
    gemm_nt<EPI_HB><<<dim3(3 * D / GBN, Bn / GBM), 256, SMEM_GEMM>>>(
        xh, Mh, bfold, nullptr, nullptr, (void*)branch, Bn, 3 * D, D);
    // launch 3 (ncu capture slot): fused triple LayerNorm -> concat
    ln3_kernel<<<Bn, 256>>>(xh, branch, gbh, concat);
    // launch 4: h1 = relu(concat @ fw1^T + fb1)
    gemm_nt<EPI_HBR><<<dim3(D / GBN, Bn / GBM), 256, SMEM_GEMM>>>(
        concat, fw1h, fb1, nullptr, nullptr, (void*)h1, Bn, D, 3 * D);
    // launch 5: fused = h1 @ fw2^T + fb2
    gemm_nt<EPI_HB><<<dim3(D / GBN, Bn / GBM), 256, SMEM_GEMM>>>(
        h1, fw2h, fb2, nullptr, nullptr, (void*)fused, Bn, D, D);
    // launch 6: h2 = relu(fused @ ffw1^T + ffb1)
    gemm_nt<EPI_HBR><<<dim3(4 * D / GBN, Bn / GBM), 256, SMEM_GEMM>>>(
        fused, ffw1h, ffb1, nullptr, nullptr, (void*)h2, Bn, 4 * D, D);
    // launch 7: out = x + fused + (h2 @ ffw2^T + ffb2)
    gemm_nt<EPI_FINAL><<<dim3(D / GBN, Bn / GBM), 256, SMEM_GEMM>>>(
        h2, ffw2h, ffb2, x, fused, d_out, Bn, D, 4 * D);
}

// round 16
// speedup vs baseline: 1.0032x; 1.0000x over previous
#include <cuda_runtime.h>
#include <cuda_fp16.h>
#include <cstdint>

#define BDIM 16384
#define DDIM 2048

// ---------------- device scratch ----------------
__device__ __align__(16) __half g_xh   [BDIM * DDIM];
__device__ __align__(16) __half g_wvT  [3][DDIM * DDIM];
__device__ __align__(16) __half g_woh  [3][DDIM * DDIM];
__device__ __align__(16) __half g_Mh   [3][DDIM * DDIM];     // folded weights = [6144, 2048]
__device__ __align__(16) float  g_bfold[3][DDIM];            // = [6144]
__device__ __align__(16) __half g_gbh  [6][DDIM];            // packed fp16 {g0,b0,g1,b1,g2,b2}
__device__ __align__(16) __half g_branch[(size_t)BDIM * 3 * DDIM];   // [B, 6144]
__device__ __align__(16) __half g_concat[(size_t)BDIM * 3 * DDIM];
__device__ __align__(16) __half g_fw1h [DDIM * 3 * DDIM];
__device__ __align__(16) __half g_fw2h [DDIM * DDIM];
__device__ __align__(16) __half g_ffw1h[4 * DDIM * DDIM];
__device__ __align__(16) __half g_ffw2h[DDIM * 4 * DDIM];
__device__ __align__(16) __half g_h1   [BDIM * DDIM];
__device__ __align__(16) __half g_fused[BDIM * DDIM];
__device__ __align__(16) __half g_h2   [(size_t)BDIM * 4 * DDIM];

// ---------------- helpers ----------------

__device__ __forceinline__ void cvt8(const float* __restrict__ in, __half* __restrict__ out, size_t i8)
{
    const float4* p = (const float4*)in + 2 * i8;
    float4 a = p[0], b = p[1];
    __half2* o = (__half2*)(out + 8 * i8);
    o[0] = __floats2half2_rn(a.x, a.y);
    o[1] = __floats2half2_rn(a.z, a.w);
    o[2] = __floats2half2_rn(b.x, b.y);
    o[3] = __floats2half2_rn(b.z, b.w);
}

// launch 0: per-branch wv transpose->fp16 and wo convert. z = branch.
__global__ void __launch_bounds__(256) prep_branch_w(
    const float* __restrict__ wv0, const float* __restrict__ wv1, const float* __restrict__ wv2,
    const float* __restrict__ wo0, const float* __restrict__ wo1, const float* __restrict__ wo2,
    __half* __restrict__ wvT, __half* __restrict__ woh)
{
    const int z = blockIdx.z;
    const float* wv = (z == 0) ? wv0 : (z == 1) ? wv1 : wv2;
    const float* wo = (z == 0) ? wo0 : (z == 1) ? wo1 : wo2;
    __half* wvTz = wvT + (size_t)z * DDIM * DDIM;
    __half* wohz = woh + (size_t)z * DDIM * DDIM;
    const int bx = blockIdx.x;
    if (bx < 4096) {
        __shared__ float t[32][33];
        const int bxc = (bx & 63) * 32;
        const int byc = (bx >> 6) * 32;
        const int tx = threadIdx.x & 31, ty = threadIdx.x >> 5;  // 32x8
#pragma unroll
        for (int i = 0; i < 4; ++i)
            t[ty + i * 8][tx] = wv[(size_t)(byc + ty + i * 8) * DDIM + bxc + tx];
        __syncthreads();
#pragma unroll
        for (int i = 0; i < 4; ++i)
            wvTz[(size_t)(bxc + ty + i * 8) * DDIM + byc + tx] = __float2half(t[tx][ty + i * 8]);
    } else {
        size_t i = (size_t)(bx - 4096) * 256 + threadIdx.x;   // 524288 chunks
        cvt8(wo, wohz, i);
    }
}

// ---------------- GEMM body (R7 config, best measured) ----------------
#define GBM 128
#define GBN 128
#define GBK 64
#define SST 72
#define STAGE_H (GBM * SST)
#define SMEM_GEMM (4 * STAGE_H * 2)   // 73728 B per CTA; 2 CTAs/SM

#define CPA16(dst, src) asm volatile("cp.async.cg.shared.global [%0], [%1], 16;" :: "r"(dst), "l"(src))

enum { EPI_HB = 0, EPI_HBR = 1, EPI_H = 2, EPI_FINAL = 3 };

template<int EPI>
__device__ __forceinline__ void gemm_body(
    const __half* __restrict__ A, const __half* __restrict__ Bm,
    const float* __restrict__ bias,
    const float* __restrict__ addX, const __half* __restrict__ addF,
    void* __restrict__ Cout, int M, int N, int K)
{
    extern __shared__ __align__(16) __half smem[];
    const int tid  = threadIdx.x;
    const int lane = tid & 31;
    const int warp = tid >> 5;
    const int wm = warp >> 2;
    const int wn = warp & 3;
    const int bm0 = blockIdx.y * GBM;
    const int bn0 = blockIdx.x * GBN;

    const int r0 = tid >> 3;
    const int c0 = (tid & 7) << 3;

    const __half* Ag = A + (size_t)(bm0 + r0) * K + c0;
    const __half* Bg = Bm + (size_t)(bn0 + r0) * K + c0;

    const uint32_t sbase = (uint32_t)__cvta_generic_to_shared(smem);
    uint32_t sA[2], sB[2];
#pragma unroll
    for (int s = 0; s < 2; ++s) {
        sA[s] = sbase + (uint32_t)(2 * s)     * STAGE_H * 2;
        sB[s] = sbase + (uint32_t)(2 * s + 1) * STAGE_H * 2;
    }
    const uint32_t so = (uint32_t)(r0 * SST + c0) * 2u;
    const uint32_t sstep = 32u * SST * 2u;

    const int KT = K / GBK;

#pragma unroll
    for (int i = 0; i < 4; ++i) {
        CPA16(sA[0] + so + i * sstep, Ag + (size_t)(32 * i) * K);
        CPA16(sB[0] + so + i * sstep, Bg + (size_t)(32 * i) * K);
    }
    asm volatile("cp.async.commit_group;");

    float acc[4][4][4];
#pragma unroll
    for (int a = 0; a < 4; ++a)
#pragma unroll
        for (int b = 0; b < 4; ++b)
#pragma unroll
            for (int q = 0; q < 4; ++q) acc[a][b][q] = 0.f;

    const int lrow = lane & 15;
    const int lcol = (lane >> 4) << 3;

    const uint32_t aBase = (uint32_t)((wm * 64 + lrow) * SST + lcol) * 2u;
    const uint32_t bBase = (uint32_t)((wn * 32 + lrow) * SST + lcol) * 2u;

    uint32_t af[2][4][4], bf[2][4][2];

#define LDFRAG(cb, sbuf, ksv)                                                              \
    do {                                                                                   \
        const uint32_t kofs = (uint32_t)((ksv) * 16 * 2);                                  \
        _Pragma("unroll")                                                                  \
        for (int mt = 0; mt < 4; ++mt) {                                                   \
            uint32_t addr = sA[sbuf] + aBase + kofs + (uint32_t)(mt * 16 * SST * 2);       \
            asm volatile("ldmatrix.sync.aligned.m8n8.x4.shared.b16 {%0,%1,%2,%3}, [%4];"   \
                         : "=r"(af[cb][mt][0]), "=r"(af[cb][mt][1]),                        \
                           "=r"(af[cb][mt][2]), "=r"(af[cb][mt][3]) : "r"(addr));          \
        }                                                                                  \
        _Pragma("unroll")                                                                  \
        for (int nt2 = 0; nt2 < 2; ++nt2) {                                                \
            uint32_t q0, q1, q2, q3;                                                       \
            uint32_t addr = sB[sbuf] + bBase + kofs + (uint32_t)(nt2 * 16 * SST * 2);      \
            asm volatile("ldmatrix.sync.aligned.m8n8.x4.shared.b16 {%0,%1,%2,%3}, [%4];"   \
                         : "=r"(q0), "=r"(q1), "=r"(q2), "=r"(q3) : "r"(addr));            \
            bf[cb][nt2 * 2 + 0][0] = q0; bf[cb][nt2 * 2 + 0][1] = q2;                      \
            bf[cb][nt2 * 2 + 1][0] = q1; bf[cb][nt2 * 2 + 1][1] = q3;                      \
        }                                                                                  \
    } while (0)

#define MMAS(cb)                                                                           \
    do {                                                                                   \
        _Pragma("unroll")                                                                  \
        for (int mt = 0; mt < 4; ++mt)                                                     \
            _Pragma("unroll")                                                              \
            for (int nt = 0; nt < 4; ++nt)                                                 \
                asm volatile("mma.sync.aligned.m16n8k16.row.col.f32.f16.f16.f32 "          \
                             "{%0,%1,%2,%3}, {%4,%5,%6,%7}, {%8,%9}, {%0,%1,%2,%3};"       \
                             : "+f"(acc[mt][nt][0]), "+f"(acc[mt][nt][1]),                  \
                               "+f"(acc[mt][nt][2]), "+f"(acc[mt][nt][3])                   \
                             : "r"(af[cb][mt][0]), "r"(af[cb][mt][1]),                      \
                               "r"(af[cb][mt][2]), "r"(af[cb][mt][3]),                      \
                               "r"(bf[cb][nt][0]), "r"(bf[cb][nt][1]));                     \
    } while (0)

    int buf = 0;
    for (int kt = 0; kt < KT; ++kt) {
        asm volatile("cp.async.wait_group 0;");
        __syncthreads();
        if (kt + 1 < KT) {
            const int koff = (kt + 1) * GBK;
#pragma unroll
            for (int i = 0; i < 4; ++i) {
                CPA16(sA[buf ^ 1] + so + i * sstep, Ag + koff + (size_t)(32 * i) * K);
                CPA16(sB[buf ^ 1] + so + i * sstep, Bg + koff + (size_t)(32 * i) * K);
            }
            asm volatile("cp.async.commit_group;");
        }
        LDFRAG(0, buf, 0);
        LDFRAG(1, buf, 1);
        MMAS(0);
        LDFRAG(0, buf, 2);
        MMAS(1);
        LDFRAG(1, buf, 3);
        MMAS(0);
        MMAS(1);
        buf ^= 1;
    }

    // epilogue
#pragma unroll
    for (int mt = 0; mt < 4; ++mt) {
        const int mrow = bm0 + wm * 64 + mt * 16 + (lane >> 2);
#pragma unroll
        for (int nt = 0; nt < 4; ++nt) {
            const int ncol = bn0 + wn * 32 + nt * 8 + ((lane & 3) << 1);
            float v0 = acc[mt][nt][0], v1 = acc[mt][nt][1];
            float v2 = acc[mt][nt][2], v3 = acc[mt][nt][3];
            if (EPI != EPI_H) {
                float b0 = bias[ncol], b1 = bias[ncol + 1];
                v0 += b0; v1 += b1; v2 += b0; v3 += b1;
            }
            if (EPI == EPI_HBR) {
                v0 = fmaxf(v0, 0.f); v1 = fmaxf(v1, 0.f);
                v2 = fmaxf(v2, 0.f); v3 = fmaxf(v3, 0.f);
            }
            const size_t i0 = (size_t)mrow * N + ncol;
            const size_t i1 = (size_t)(mrow + 8) * N + ncol;
            if (EPI == EPI_FINAL) {
                float* O = (float*)Cout;
                float2 x0 = *(const float2*)(addX + i0);
                float2 x1 = *(const float2*)(addX + i1);
                float2 f0 = __half22float2(*(const __half2*)(addF + i0));
                float2 f1 = __half22float2(*(const __half2*)(addF + i1));
                *(float2*)(O + i0) = make_float2(v0 + x0.x + f0.x, v1 + x0.y + f0.y);
                *(float2*)(O + i1) = make_float2(v2 + x1.x + f1.x, v3 + x1.y + f1.y);
            } else {
                __half* O = (__half*)Cout;
                *(__half2*)(O + i0) = __floats2half2_rn(v0, v1);
                *(__half2*)(O + i1) = __floats2half2_rn(v2, v3);
            }
        }
    }
}

template<int EPI>
__global__ void __launch_bounds__(256, 2)
gemm_nt(const __half* __restrict__ A, const __half* __restrict__ Bm,
        const float* __restrict__ bias,
        const float* __restrict__ addX, const __half* __restrict__ addF,
        void* __restrict__ Cout, int M, int N, int K)
{
    gemm_body<EPI>(A, Bm, bias, addX, addF, Cout, M, N, K);
}

// launch 1: fold GEMM (z<3) + conversions + bias fold + gamma/beta pack (z==3)
#define XCH 4194304u
#define C1 1572864u
#define C2 (C1 + 524288u)
#define C3 (C2 + 2097152u)
#define C4 (C3 + 2097152u)
__global__ void __launch_bounds__(256, 2)
fold_prep_gemm(
    const __half* __restrict__ woh, const __half* __restrict__ wvT, __half* __restrict__ Mh,
    const float* __restrict__ x, __half* __restrict__ xh,
    const float* __restrict__ fw1, __half* __restrict__ fw1h,
    const float* __restrict__ fw2, __half* __restrict__ fw2h,
    const float* __restrict__ ffw1, __half* __restrict__ ffw1h,
    const float* __restrict__ ffw2, __half* __restrict__ ffw2h,
    const float* __restrict__ wo0, const float* __restrict__ wo1, const float* __restrict__ wo2,
    const float* __restrict__ bv0, const float* __restrict__ bv1, const float* __restrict__ bv2,
    const float* __restrict__ bo0, const float* __restrict__ bo1, const float* __restrict__ bo2,
    float* __restrict__ bfold,
    const float* __restrict__ g0, const float* __restrict__ bb0,
    const float* __restrict__ g1, const float* __restrict__ bb1,
    const float* __restrict__ g2, const float* __restrict__ bb2,
    __half* __restrict__ gbh)
{
    const int z = blockIdx.z;
    const size_t DD = (size_t)DDIM * DDIM;
    if (z < 3) {
        gemm_body<EPI_H>(woh + DD * z, wvT + DD * z, nullptr, nullptr, nullptr,
                         (void*)(Mh + DD * z), DDIM, DDIM, DDIM);
        return;
    }
    const uint32_t id = blockIdx.y * 16u + blockIdx.x;   // 0..255
    const uint32_t gt = id * 256u + threadIdx.x;         // 0..65535
    const uint32_t GS = 65536u;

    // fold bias: warp per row, 3 branches
    {
        const int warp = threadIdx.x >> 5, lane = threadIdx.x & 31;
        const int gw = (int)(id * 8u) + warp;            // 0..2047
        const float* wos[3] = {wo0, wo1, wo2};
        const float* bvs[3] = {bv0, bv1, bv2};
        const float* bos[3] = {bo0, bo1, bo2};
#pragma unroll
        for (int zz = 0; zz < 3; ++zz) {
            float s = 0.f;
            const float* wo = wos[zz];
            for (int k = lane; k < DDIM; k += 32) s += bvs[zz][k] * wo[(size_t)gw * DDIM + k];
#pragma unroll
            for (int o = 16; o; o >>= 1) s += __shfl_xor_sync(0xffffffffu, s, o);
            if (lane == 0) bfold[(size_t)zz * DDIM + gw] = s + bos[zz][gw];
        }
    }
    // pack gamma/beta to fp16: 6 arrays x 256 chunks = 1536 chunks
    if (gt < 1536u) {
        const float* srcs[6] = {g0, bb0, g1, bb1, g2, bb2};
        const uint32_t which = gt >> 8;
        cvt8(srcs[which], gbh + (size_t)which * DDIM, gt & 255u);
    }
    for (uint32_t i = gt; i < XCH; i += GS) cvt8(x, xh, i);
    for (uint32_t i = gt; i < C4; i += GS) {
        if      (i < C1) cvt8(fw1,  fw1h,  i);
        else if (i < C2) cvt8(fw2,  fw2h,  i - C1);
        else if (i < C3) cvt8(ffw1, ffw1h, i - C2);
        else             cvt8(ffw2, ffw2h, i - C3);
    }
}

// launch 3: one-pass fused triple LayerNorm, 16B-vectorized, fp16 gamma/beta,
// x/branch rows kept PACKED in registers (lower reg pressure -> higher occupancy).
__global__ void __launch_bounds__(256) ln3_kernel(
    const __half* __restrict__ xh,
    const __half* __restrict__ brc,
    const __half* __restrict__ gbh,
    __half* __restrict__ concat)
{
    const int row  = blockIdx.x;
    const int tid  = threadIdx.x;
    const int c    = tid * 8;
    const int warp = tid >> 5, lane = tid & 31;
    __shared__ float red[6][9];

    const uint4 xr = *(const uint4*)(xh + (size_t)row * DDIM + c);
    uint4 br[3];
    float st[6];
#pragma unroll
    for (int j = 0; j < 3; ++j) {
        br[j] = *(const uint4*)(brc + (size_t)row * (3 * DDIM) + (size_t)j * DDIM + c);
        const __half2* xp = (const __half2*)&xr;
        const __half2* bp = (const __half2*)&br[j];
        float sum = 0.f, sq = 0.f;
#pragma unroll
        for (int q = 0; q < 4; ++q) {
            float2 fx = __half22float2(xp[q]);
            float2 fb = __half22float2(bp[q]);
            float a0 = fx.x + fb.x;
            float a1 = fx.y + fb.y;
            sum += a0 + a1;
            sq  += a0 * a0 + a1 * a1;
        }
        st[2*j] = sum; st[2*j+1] = sq;
    }
#pragma unroll
    for (int o = 16; o; o >>= 1) {
#pragma unroll
        for (int q = 0; q < 6; ++q) st[q] += __shfl_xor_sync(0xffffffffu, st[q], o);
    }
    if (lane == 0) {
#pragma unroll
        for (int q = 0; q < 6; ++q) red[q][warp] = st[q];
    }
    __syncthreads();
    if (tid < 6) {
        float a = 0.f;
#pragma unroll
        for (int i = 0; i < 8; ++i) a += red[tid][i];
        red[tid][8] = a;
    }
    __syncthreads();

#pragma unroll
    for (int j = 0; j < 3; ++j) {
        const float mean = red[2*j][8] * (1.0f / DDIM);
        const float var  = red[2*j+1][8] * (1.0f / DDIM) - mean * mean;
        const float inv  = rsqrtf(var + 1e-5f);
        uint4 gw4 = *(const uint4*)(gbh + (size_t)(2*j)     * DDIM + c);
        uint4 bw4 = *(const uint4*)(gbh + (size_t)(2*j + 1) * DDIM + c);
        const __half2* gp  = (const __half2*)&gw4;
        const __half2* bp2 = (const __half2*)&bw4;
        const __half2* xp  = (const __half2*)&xr;
        const __half2* bp  = (const __half2*)&br[j];
        uint4 outw;
        __half2* ow = (__half2*)&outw;
#pragma unroll
        for (int q = 0; q < 4; ++q) {
            float2 fx = __half22float2(xp[q]);
            float2 fb = __half22float2(bp[q]);
            float2 gf = __half22float2(gp[q]);
            float2 bf = __half22float2(bp2[q]);
            float a0 = fx.x + fb.x;
            float a1 = fx.y + fb.y;
            ow[q] = __floats2half2_rn((a0 - mean) * inv * gf.x + bf.x,
                                      (a1 - mean) * inv * gf.y + bf.y);
        }
        *(uint4*)(concat + (size_t)row * (3 * DDIM) + (size_t)j * DDIM + c) = outw;
    }
}

// ---------------- launcher ----------------
extern "C" void kernel_launch(void* const* d_in, const int* in_sizes, int n_in,
                              void* d_out, int out_size)
{
    (void)in_sizes; (void)n_in; (void)out_size;
    const float* x     = (const float*)d_in[0];
    const float* wv[3] = {(const float*)d_in[1], (const float*)d_in[5], (const float*)d_in[9]};
    const float* bv[3] = {(const float*)d_in[2], (const float*)d_in[6], (const float*)d_in[10]};
    const float* wo[3] = {(const float*)d_in[3], (const float*)d_in[7], (const float*)d_in[11]};
    const float* bo[3] = {(const float*)d_in[4], (const float*)d_in[8], (const float*)d_in[12]};
    const float* g[3]  = {(const float*)d_in[13], (const float*)d_in[15], (const float*)d_in[17]};
    const float* bb[3] = {(const float*)d_in[14], (const float*)d_in[16], (const float*)d_in[18]};
    const float* fw1  = (const float*)d_in[19]; const float* fb1  = (const float*)d_in[20];
    const float* fw2  = (const float*)d_in[21]; const float* fb2  = (const float*)d_in[22];
    const float* ffw1 = (const float*)d_in[23]; const float* ffb1 = (const float*)d_in[24];
    const float* ffw2 = (const float*)d_in[25]; const float* ffb2 = (const float*)d_in[26];

    void *p;
    __half *xh, *wvT, *woh, *Mh, *branch, *concat, *fw1h, *fw2h, *ffw1h, *ffw2h, *h1, *fused, *h2, *gbh;
    float *bfold;
    cudaGetSymbolAddress(&p, g_xh);     xh     = (__half*)p;
    cudaGetSymbolAddress(&p, g_wvT);    wvT    = (__half*)p;
    cudaGetSymbolAddress(&p, g_woh);    woh    = (__half*)p;
    cudaGetSymbolAddress(&p, g_Mh);     Mh     = (__half*)p;
    cudaGetSymbolAddress(&p, g_bfold);  bfold  = (float*)p;
    cudaGetSymbolAddress(&p, g_gbh);    gbh    = (__half*)p;
    cudaGetSymbolAddress(&p, g_branch); branch = (__half*)p;
    cudaGetSymbolAddress(&p, g_concat); concat = (__half*)p;
    cudaGetSymbolAddress(&p, g_fw1h);   fw1h   = (__half*)p;
    cudaGetSymbolAddress(&p, g_fw2h);   fw2h   = (__half*)p;
    cudaGetSymbolAddress(&p, g_ffw1h);  ffw1h  = (__half*)p;
    cudaGetSymbolAddress(&p, g_ffw2h);  ffw2h  = (__half*)p;
    cudaGetSymbolAddress(&p, g_h1);     h1     = (__half*)p;
    cudaGetSymbolAddress(&p, g_fused);  fused  = (__half*)p;
    cudaGetSymbolAddress(&p, g_h2);     h2     = (__half*)p;

    cudaFuncSetAttribute(gemm_nt<EPI_HB>,    cudaFuncAttributeMaxDynamicSharedMemorySize, SMEM_GEMM);
    cudaFuncSetAttribute(gemm_nt<EPI_HBR>,   cudaFuncAttributeMaxDynamicSharedMemorySize, SMEM_GEMM);
    cudaFuncSetAttribute(gemm_nt<EPI_FINAL>, cudaFuncAttributeMaxDynamicSharedMemorySize, SMEM_GEMM);
    cudaFuncSetAttribute(fold_prep_gemm,     cudaFuncAttributeMaxDynamicSharedMemorySize, SMEM_GEMM);

    const int D  = DDIM;
    const int Bn = BDIM;

    // launch 0: branch weight transpose + wo convert
    prep_branch_w<<<dim3(4096 + 2048, 1, 3), 256>>>(
        wv[0], wv[1], wv[2], wo[0], wo[1], wo[2], wvT, woh);
    // launch 1: fold GEMM (z<3) + conversions + bias fold + gamma/beta pack (z==3)
    fold_prep_gemm<<<dim3(16, 16, 4), 256, SMEM_GEMM>>>(
        woh, wvT, Mh,
        x, xh, fw1, fw1h, fw2, fw2h, ffw1, ffw1h, ffw2, ffw2h,
        wo[0], wo[1], wo[2], bv[0], bv[1], bv[2], bo[0], bo[1], bo[2], bfold,
        g[0], bb[0], g[1], bb[1], g[2], bb[2], gbh);
    // launch 2: merged branch GEMM [B,6144]
    gemm_nt<EPI_HB><<<dim3(3 * D / GBN, Bn / GBM), 256, SMEM_GEMM>>>(
        xh, Mh, bfold, nullptr, nullptr, (void*)branch, Bn, 3 * D, D);
    // launch 3 (ncu capture slot): fused triple LayerNorm -> concat
    ln3_kernel<<<Bn, 256>>>(xh, branch, gbh, concat);
    // launch 4: h1 = relu(concat @ fw1^T + fb1)
    gemm_nt<EPI_HBR><<<dim3(D / GBN, Bn / GBM), 256, SMEM_GEMM>>>(
        concat, fw1h, fb1, nullptr, nullptr, (void*)h1, Bn, D, 3 * D);
    // launch 5: fused = h1 @ fw2^T + fb2
    gemm_nt<EPI_HB><<<dim3(D / GBN, Bn / GBM), 256, SMEM_GEMM>>>(
        h1, fw2h, fb2, nullptr, nullptr, (void*)fused, Bn, D, D);
    // launch 6: h2 = relu(fused @ ffw1^T + ffb1)
    gemm_nt<EPI_HBR><<<dim3(4 * D / GBN, Bn / GBM), 256, SMEM_GEMM>>>(
        fused, ffw1h, ffb1, nullptr, nullptr, (void*)h2, Bn, 4 * D, D);
    // launch 7: out = x + fused + (h2 @ ffw2^T + ffb2)
    gemm_nt<EPI_FINAL><<<dim3(D / GBN, Bn / GBM), 256, SMEM_GEMM>>>(
        h2, ffw2h, ffb2, x, fused, d_out, Bn, D, 4 * D);
}

// round 17
// speedup vs baseline: 1.0052x; 1.0019x over previous
#include <cuda_runtime.h>
#include <cuda_fp16.h>
#include <cstdint>

#define BDIM 16384
#define DDIM 2048

// ---------------- device scratch ----------------
__device__ __align__(16) __half g_xh   [BDIM * DDIM];
__device__ __align__(16) __half g_wvT  [3][DDIM * DDIM];
__device__ __align__(16) __half g_woh  [3][DDIM * DDIM];
__device__ __align__(16) __half g_Mh   [3][DDIM * DDIM];     // folded weights = [6144, 2048]
__device__ __align__(16) float  g_bfold[3][DDIM];            // = [6144]
__device__ __align__(16) __half g_gbh  [6][DDIM];            // packed fp16 {g0,b0,g1,b1,g2,b2}
__device__ __align__(16) __half g_branch[(size_t)BDIM * 3 * DDIM];   // [B, 6144]
__device__ __align__(16) __half g_concat[(size_t)BDIM * 3 * DDIM];
__device__ __align__(16) __half g_fw1h [DDIM * 3 * DDIM];
__device__ __align__(16) __half g_fw2h [DDIM * DDIM];
__device__ __align__(16) __half g_ffw1h[4 * DDIM * DDIM];
__device__ __align__(16) __half g_ffw2h[DDIM * 4 * DDIM];
__device__ __align__(16) __half g_h1   [BDIM * DDIM];
__device__ __align__(16) __half g_fused[BDIM * DDIM];
__device__ __align__(16) __half g_h2   [(size_t)BDIM * 4 * DDIM];

// ---------------- helpers ----------------

__device__ __forceinline__ void cvt8(const float* __restrict__ in, __half* __restrict__ out, size_t i8)
{
    const float4* p = (const float4*)in + 2 * i8;
    float4 a = p[0], b = p[1];
    __half2* o = (__half2*)(out + 8 * i8);
    o[0] = __floats2half2_rn(a.x, a.y);
    o[1] = __floats2half2_rn(a.z, a.w);
    o[2] = __floats2half2_rn(b.x, b.y);
    o[3] = __floats2half2_rn(b.z, b.w);
}

// launch 0: per-branch wv transpose->fp16 and wo convert. z = branch.
__global__ void __launch_bounds__(256) prep_branch_w(
    const float* __restrict__ wv0, const float* __restrict__ wv1, const float* __restrict__ wv2,
    const float* __restrict__ wo0, const float* __restrict__ wo1, const float* __restrict__ wo2,
    __half* __restrict__ wvT, __half* __restrict__ woh)
{
    const int z = blockIdx.z;
    const float* wv = (z == 0) ? wv0 : (z == 1) ? wv1 : wv2;
    const float* wo = (z == 0) ? wo0 : (z == 1) ? wo1 : wo2;
    __half* wvTz = wvT + (size_t)z * DDIM * DDIM;
    __half* wohz = woh + (size_t)z * DDIM * DDIM;
    const int bx = blockIdx.x;
    if (bx < 4096) {
        __shared__ float t[32][33];
        const int bxc = (bx & 63) * 32;
        const int byc = (bx >> 6) * 32;
        const int tx = threadIdx.x & 31, ty = threadIdx.x >> 5;  // 32x8
#pragma unroll
        for (int i = 0; i < 4; ++i)
            t[ty + i * 8][tx] = wv[(size_t)(byc + ty + i * 8) * DDIM + bxc + tx];
        __syncthreads();
#pragma unroll
        for (int i = 0; i < 4; ++i)
            wvTz[(size_t)(bxc + ty + i * 8) * DDIM + byc + tx] = __float2half(t[tx][ty + i * 8]);
    } else {
        size_t i = (size_t)(bx - 4096) * 256 + threadIdx.x;   // 524288 chunks
        cvt8(wo, wohz, i);
    }
}

// ---------------- GEMM body (R7 config, best measured) ----------------
#define GBM 128
#define GBN 128
#define GBK 64
#define SST 72
#define STAGE_H (GBM * SST)
#define SMEM_GEMM (4 * STAGE_H * 2)   // 73728 B per CTA; 2 CTAs/SM

#define CPA16(dst, src) asm volatile("cp.async.cg.shared.global [%0], [%1], 16;" :: "r"(dst), "l"(src))

enum { EPI_HB = 0, EPI_HBR = 1, EPI_H = 2, EPI_FINAL = 3 };

template<int EPI>
__device__ __forceinline__ void gemm_body(
    const __half* __restrict__ A, const __half* __restrict__ Bm,
    const float* __restrict__ bias,
    const float* __restrict__ addX, const __half* __restrict__ addF,
    void* __restrict__ Cout, int M, int N, int K)
{
    extern __shared__ __align__(16) __half smem[];
    const int tid  = threadIdx.x;
    const int lane = tid & 31;
    const int warp = tid >> 5;
    const int wm = warp >> 2;
    const int wn = warp & 3;
    const int bm0 = blockIdx.y * GBM;
    const int bn0 = blockIdx.x * GBN;

    const int r0 = tid >> 3;
    const int c0 = (tid & 7) << 3;

    const __half* Ag = A + (size_t)(bm0 + r0) * K + c0;
    const __half* Bg = Bm + (size_t)(bn0 + r0) * K + c0;

    const uint32_t sbase = (uint32_t)__cvta_generic_to_shared(smem);
    uint32_t sA[2], sB[2];
#pragma unroll
    for (int s = 0; s < 2; ++s) {
        sA[s] = sbase + (uint32_t)(2 * s)     * STAGE_H * 2;
        sB[s] = sbase + (uint32_t)(2 * s + 1) * STAGE_H * 2;
    }
    const uint32_t so = (uint32_t)(r0 * SST + c0) * 2u;
    const uint32_t sstep = 32u * SST * 2u;

    const int KT = K / GBK;

#pragma unroll
    for (int i = 0; i < 4; ++i) {
        CPA16(sA[0] + so + i * sstep, Ag + (size_t)(32 * i) * K);
        CPA16(sB[0] + so + i * sstep, Bg + (size_t)(32 * i) * K);
    }
    asm volatile("cp.async.commit_group;");

    float acc[4][4][4];
#pragma unroll
    for (int a = 0; a < 4; ++a)
#pragma unroll
        for (int b = 0; b < 4; ++b)
#pragma unroll
            for (int q = 0; q < 4; ++q) acc[a][b][q] = 0.f;

    const int lrow = lane & 15;
    const int lcol = (lane >> 4) << 3;

    const uint32_t aBase = (uint32_t)((wm * 64 + lrow) * SST + lcol) * 2u;
    const uint32_t bBase = (uint32_t)((wn * 32 + lrow) * SST + lcol) * 2u;

    uint32_t af[2][4][4], bf[2][4][2];

#define LDFRAG(cb, sbuf, ksv)                                                              \
    do {                                                                                   \
        const uint32_t kofs = (uint32_t)((ksv) * 16 * 2);                                  \
        _Pragma("unroll")                                                                  \
        for (int mt = 0; mt < 4; ++mt) {                                                   \
            uint32_t addr = sA[sbuf] + aBase + kofs + (uint32_t)(mt * 16 * SST * 2);       \
            asm volatile("ldmatrix.sync.aligned.m8n8.x4.shared.b16 {%0,%1,%2,%3}, [%4];"   \
                         : "=r"(af[cb][mt][0]), "=r"(af[cb][mt][1]),                        \
                           "=r"(af[cb][mt][2]), "=r"(af[cb][mt][3]) : "r"(addr));          \
        }                                                                                  \
        _Pragma("unroll")                                                                  \
        for (int nt2 = 0; nt2 < 2; ++nt2) {                                                \
            uint32_t q0, q1, q2, q3;                                                       \
            uint32_t addr = sB[sbuf] + bBase + kofs + (uint32_t)(nt2 * 16 * SST * 2);      \
            asm volatile("ldmatrix.sync.aligned.m8n8.x4.shared.b16 {%0,%1,%2,%3}, [%4];"   \
                         : "=r"(q0), "=r"(q1), "=r"(q2), "=r"(q3) : "r"(addr));            \
            bf[cb][nt2 * 2 + 0][0] = q0; bf[cb][nt2 * 2 + 0][1] = q2;                      \
            bf[cb][nt2 * 2 + 1][0] = q1; bf[cb][nt2 * 2 + 1][1] = q3;                      \
        }                                                                                  \
    } while (0)

#define MMAS(cb)                                                                           \
    do {                                                                                   \
        _Pragma("unroll")                                                                  \
        for (int mt = 0; mt < 4; ++mt)                                                     \
            _Pragma("unroll")                                                              \
            for (int nt = 0; nt < 4; ++nt)                                                 \
                asm volatile("mma.sync.aligned.m16n8k16.row.col.f32.f16.f16.f32 "          \
                             "{%0,%1,%2,%3}, {%4,%5,%6,%7}, {%8,%9}, {%0,%1,%2,%3};"       \
                             : "+f"(acc[mt][nt][0]), "+f"(acc[mt][nt][1]),                  \
                               "+f"(acc[mt][nt][2]), "+f"(acc[mt][nt][3])                   \
                             : "r"(af[cb][mt][0]), "r"(af[cb][mt][1]),                      \
                               "r"(af[cb][mt][2]), "r"(af[cb][mt][3]),                      \
                               "r"(bf[cb][nt][0]), "r"(bf[cb][nt][1]));                     \
    } while (0)

    int buf = 0;
    for (int kt = 0; kt < KT; ++kt) {
        asm volatile("cp.async.wait_group 0;");
        __syncthreads();
        if (kt + 1 < KT) {
            const int koff = (kt + 1) * GBK;
#pragma unroll
            for (int i = 0; i < 4; ++i) {
                CPA16(sA[buf ^ 1] + so + i * sstep, Ag + koff + (size_t)(32 * i) * K);
                CPA16(sB[buf ^ 1] + so + i * sstep, Bg + koff + (size_t)(32 * i) * K);
            }
            asm volatile("cp.async.commit_group;");
        }
        LDFRAG(0, buf, 0);
        LDFRAG(1, buf, 1);
        MMAS(0);
        LDFRAG(0, buf, 2);
        MMAS(1);
        LDFRAG(1, buf, 3);
        MMAS(0);
        MMAS(1);
        buf ^= 1;
    }

    // epilogue
#pragma unroll
    for (int mt = 0; mt < 4; ++mt) {
        const int mrow = bm0 + wm * 64 + mt * 16 + (lane >> 2);
#pragma unroll
        for (int nt = 0; nt < 4; ++nt) {
            const int ncol = bn0 + wn * 32 + nt * 8 + ((lane & 3) << 1);
            float v0 = acc[mt][nt][0], v1 = acc[mt][nt][1];
            float v2 = acc[mt][nt][2], v3 = acc[mt][nt][3];
            if (EPI != EPI_H) {
                float b0 = bias[ncol], b1 = bias[ncol + 1];
                v0 += b0; v1 += b1; v2 += b0; v3 += b1;
            }
            if (EPI == EPI_HBR) {
                v0 = fmaxf(v0, 0.f); v1 = fmaxf(v1, 0.f);
                v2 = fmaxf(v2, 0.f); v3 = fmaxf(v3, 0.f);
            }
            const size_t i0 = (size_t)mrow * N + ncol;
            const size_t i1 = (size_t)(mrow + 8) * N + ncol;
            if (EPI == EPI_FINAL) {
                float* O = (float*)Cout;
                float2 x0 = *(const float2*)(addX + i0);
                float2 x1 = *(const float2*)(addX + i1);
                float2 f0 = __half22float2(*(const __half2*)(addF + i0));
                float2 f1 = __half22float2(*(const __half2*)(addF + i1));
                *(float2*)(O + i0) = make_float2(v0 + x0.x + f0.x, v1 + x0.y + f0.y);
                *(float2*)(O + i1) = make_float2(v2 + x1.x + f1.x, v3 + x1.y + f1.y);
            } else {
                __half* O = (__half*)Cout;
                *(__half2*)(O + i0) = __floats2half2_rn(v0, v1);
                *(__half2*)(O + i1) = __floats2half2_rn(v2, v3);
            }
        }
    }
}

template<int EPI>
__global__ void __launch_bounds__(256, 2)
gemm_nt(const __half* __restrict__ A, const __half* __restrict__ Bm,
        const float* __restrict__ bias,
        const float* __restrict__ addX, const __half* __restrict__ addF,
        void* __restrict__ Cout, int M, int N, int K)
{
    gemm_body<EPI>(A, Bm, bias, addX, addF, Cout, M, N, K);
}

// launch 1: fold GEMM (z<3) + conversions + bias fold + gamma/beta pack (z==3)
#define XCH 4194304u
#define C1 1572864u
#define C2 (C1 + 524288u)
#define C3 (C2 + 2097152u)
#define C4 (C3 + 2097152u)
__global__ void __launch_bounds__(256, 2)
fold_prep_gemm(
    const __half* __restrict__ woh, const __half* __restrict__ wvT, __half* __restrict__ Mh,
    const float* __restrict__ x, __half* __restrict__ xh,
    const float* __restrict__ fw1, __half* __restrict__ fw1h,
    const float* __restrict__ fw2, __half* __restrict__ fw2h,
    const float* __restrict__ ffw1, __half* __restrict__ ffw1h,
    const float* __restrict__ ffw2, __half* __restrict__ ffw2h,
    const float* __restrict__ wo0, const float* __restrict__ wo1, const float* __restrict__ wo2,
    const float* __restrict__ bv0, const float* __restrict__ bv1, const float* __restrict__ bv2,
    const float* __restrict__ bo0, const float* __restrict__ bo1, const float* __restrict__ bo2,
    float* __restrict__ bfold,
    const float* __restrict__ g0, const float* __restrict__ bb0,
    const float* __restrict__ g1, const float* __restrict__ bb1,
    const float* __restrict__ g2, const float* __restrict__ bb2,
    __half* __restrict__ gbh)
{
    const int z = blockIdx.z;
    const size_t DD = (size_t)DDIM * DDIM;
    if (z < 3) {
        gemm_body<EPI_H>(woh + DD * z, wvT + DD * z, nullptr, nullptr, nullptr,
                         (void*)(Mh + DD * z), DDIM, DDIM, DDIM);
        return;
    }
    const uint32_t id = blockIdx.y * 16u + blockIdx.x;   // 0..255
    const uint32_t gt = id * 256u + threadIdx.x;         // 0..65535
    const uint32_t GS = 65536u;

    // fold bias: warp per row, 3 branches
    {
        const int warp = threadIdx.x >> 5, lane = threadIdx.x & 31;
        const int gw = (int)(id * 8u) + warp;            // 0..2047
        const float* wos[3] = {wo0, wo1, wo2};
        const float* bvs[3] = {bv0, bv1, bv2};
        const float* bos[3] = {bo0, bo1, bo2};
#pragma unroll
        for (int zz = 0; zz < 3; ++zz) {
            float s = 0.f;
            const float* wo = wos[zz];
            for (int k = lane; k < DDIM; k += 32) s += bvs[zz][k] * wo[(size_t)gw * DDIM + k];
#pragma unroll
            for (int o = 16; o; o >>= 1) s += __shfl_xor_sync(0xffffffffu, s, o);
            if (lane == 0) bfold[(size_t)zz * DDIM + gw] = s + bos[zz][gw];
        }
    }
    // pack gamma/beta to fp16: 6 arrays x 256 chunks = 1536 chunks
    if (gt < 1536u) {
        const float* srcs[6] = {g0, bb0, g1, bb1, g2, bb2};
        const uint32_t which = gt >> 8;
        cvt8(srcs[which], gbh + (size_t)which * DDIM, gt & 255u);
    }
    for (uint32_t i = gt; i < XCH; i += GS) cvt8(x, xh, i);
    for (uint32_t i = gt; i < C4; i += GS) {
        if      (i < C1) cvt8(fw1,  fw1h,  i);
        else if (i < C2) cvt8(fw2,  fw2h,  i - C1);
        else if (i < C3) cvt8(ffw1, ffw1h, i - C2);
        else             cvt8(ffw2, ffw2h, i - C3);
    }
}

// launch 3: one-pass fused triple LayerNorm, 16B-vectorized, fp16 gamma/beta.
// __launch_bounds__(256, 6) forces regs <= 42 -> 6 CTAs/SM -> higher occupancy
// for this DRAM-bound kernel.
__global__ void __launch_bounds__(256, 6) ln3_kernel(
    const __half* __restrict__ xh,
    const __half* __restrict__ brc,
    const __half* __restrict__ gbh,
    __half* __restrict__ concat)
{
    const int row  = blockIdx.x;
    const int tid  = threadIdx.x;
    const int c    = tid * 8;
    const int warp = tid >> 5, lane = tid & 31;
    __shared__ float red[6][9];

    const uint4 xr = *(const uint4*)(xh + (size_t)row * DDIM + c);
    uint4 br[3];
    float st[6];
#pragma unroll
    for (int j = 0; j < 3; ++j) {
        br[j] = *(const uint4*)(brc + (size_t)row * (3 * DDIM) + (size_t)j * DDIM + c);
        const __half2* xp = (const __half2*)&xr;
        const __half2* bp = (const __half2*)&br[j];
        float sum = 0.f, sq = 0.f;
#pragma unroll
        for (int q = 0; q < 4; ++q) {
            float2 fx = __half22float2(xp[q]);
            float2 fb = __half22float2(bp[q]);
            float a0 = fx.x + fb.x;
            float a1 = fx.y + fb.y;
            sum += a0 + a1;
            sq  += a0 * a0 + a1 * a1;
        }
        st[2*j] = sum; st[2*j+1] = sq;
    }
#pragma unroll
    for (int o = 16; o; o >>= 1) {
#pragma unroll
        for (int q = 0; q < 6; ++q) st[q] += __shfl_xor_sync(0xffffffffu, st[q], o);
    }
    if (lane == 0) {
#pragma unroll
        for (int q = 0; q < 6; ++q) red[q][warp] = st[q];
    }
    __syncthreads();
    if (tid < 6) {
        float a = 0.f;
#pragma unroll
        for (int i = 0; i < 8; ++i) a += red[tid][i];
        red[tid][8] = a;
    }
    __syncthreads();

#pragma unroll
    for (int j = 0; j < 3; ++j) {
        const float mean = red[2*j][8] * (1.0f / DDIM);
        const float var  = red[2*j+1][8] * (1.0f / DDIM) - mean * mean;
        const float inv  = rsqrtf(var + 1e-5f);
        uint4 gw4 = *(const uint4*)(gbh + (size_t)(2*j)     * DDIM + c);
        uint4 bw4 = *(const uint4*)(gbh + (size_t)(2*j + 1) * DDIM + c);
        const __half2* gp  = (const __half2*)&gw4;
        const __half2* bp2 = (const __half2*)&bw4;
        const __half2* xp  = (const __half2*)&xr;
        const __half2* bp  = (const __half2*)&br[j];
        uint4 outw;
        __half2* ow = (__half2*)&outw;
#pragma unroll
        for (int q = 0; q < 4; ++q) {
            float2 fx = __half22float2(xp[q]);
            float2 fb = __half22float2(bp[q]);
            float2 gf = __half22float2(gp[q]);
            float2 bf = __half22float2(bp2[q]);
            float a0 = fx.x + fb.x;
            float a1 = fx.y + fb.y;
            ow[q] = __floats2half2_rn((a0 - mean) * inv * gf.x + bf.x,
                                      (a1 - mean) * inv * gf.y + bf.y);
        }
        *(uint4*)(concat + (size_t)row * (3 * DDIM) + (size_t)j * DDIM + c) = outw;
    }
}

// ---------------- launcher ----------------
extern "C" void kernel_launch(void* const* d_in, const int* in_sizes, int n_in,
                              void* d_out, int out_size)
{
    (void)in_sizes; (void)n_in; (void)out_size;
    const float* x     = (const float*)d_in[0];
    const float* wv[3] = {(const float*)d_in[1], (const float*)d_in[5], (const float*)d_in[9]};
    const float* bv[3] = {(const float*)d_in[2], (const float*)d_in[6], (const float*)d_in[10]};
    const float* wo[3] = {(const float*)d_in[3], (const float*)d_in[7], (const float*)d_in[11]};
    const float* bo[3] = {(const float*)d_in[4], (const float*)d_in[8], (const float*)d_in[12]};
    const float* g[3]  = {(const float*)d_in[13], (const float*)d_in[15], (const float*)d_in[17]};
    const float* bb[3] = {(const float*)d_in[14], (const float*)d_in[16], (const float*)d_in[18]};
    const float* fw1  = (const float*)d_in[19]; const float* fb1  = (const float*)d_in[20];
    const float* fw2  = (const float*)d_in[21]; const float* fb2  = (const float*)d_in[22];
    const float* ffw1 = (const float*)d_in[23]; const float* ffb1 = (const float*)d_in[24];
    const float* ffw2 = (const float*)d_in[25]; const float* ffb2 = (const float*)d_in[26];

    void *p;
    __half *xh, *wvT, *woh, *Mh, *branch, *concat, *fw1h, *fw2h, *ffw1h, *ffw2h, *h1, *fused, *h2, *gbh;
    float *bfold;
    cudaGetSymbolAddress(&p, g_xh);     xh     = (__half*)p;
    cudaGetSymbolAddress(&p, g_wvT);    wvT    = (__half*)p;
    cudaGetSymbolAddress(&p, g_woh);    woh    = (__half*)p;
    cudaGetSymbolAddress(&p, g_Mh);     Mh     = (__half*)p;
    cudaGetSymbolAddress(&p, g_bfold);  bfold  = (float*)p;
    cudaGetSymbolAddress(&p, g_gbh);    gbh    = (__half*)p;
    cudaGetSymbolAddress(&p, g_branch); branch = (__half*)p;
    cudaGetSymbolAddress(&p, g_concat); concat = (__half*)p;
    cudaGetSymbolAddress(&p, g_fw1h);   fw1h   = (__half*)p;
    cudaGetSymbolAddress(&p, g_fw2h);   fw2h   = (__half*)p;
    cudaGetSymbolAddress(&p, g_ffw1h);  ffw1h  = (__half*)p;
    cudaGetSymbolAddress(&p, g_ffw2h);  ffw2h  = (__half*)p;
    cudaGetSymbolAddress(&p, g_h1);     h1     = (__half*)p;
    cudaGetSymbolAddress(&p, g_fused);  fused  = (__half*)p;
    cudaGetSymbolAddress(&p, g_h2);     h2     = (__half*)p;

    cudaFuncSetAttribute(gemm_nt<EPI_HB>,    cudaFuncAttributeMaxDynamicSharedMemorySize, SMEM_GEMM);
    cudaFuncSetAttribute(gemm_nt<EPI_HBR>,   cudaFuncAttributeMaxDynamicSharedMemorySize, SMEM_GEMM);
    cudaFuncSetAttribute(gemm_nt<EPI_FINAL>, cudaFuncAttributeMaxDynamicSharedMemorySize, SMEM_GEMM);
    cudaFuncSetAttribute(fold_prep_gemm,     cudaFuncAttributeMaxDynamicSharedMemorySize, SMEM_GEMM);

    const int D  = DDIM;
    const int Bn = BDIM;

    // launch 0: branch weight transpose + wo convert
    prep_branch_w<<<dim3(4096 + 2048, 1, 3), 256>>>(
        wv[0], wv[1], wv[2], wo[0], wo[1], wo[2], wvT, woh);
    // launch 1: fold GEMM (z<3) + conversions + bias fold + gamma/beta pack (z==3)
    fold_prep_gemm<<<dim3(16, 16, 4), 256, SMEM_GEMM>>>(
        woh, wvT, Mh,
        x, xh, fw1, fw1h, fw2, fw2h, ffw1, ffw1h, ffw2, ffw2h,
        wo[0], wo[1], wo[2], bv[0], bv[1], bv[2], bo[0], bo[1], bo[2], bfold,
        g[0], bb[0], g[1], bb[1], g[2], bb[2], gbh);
    // launch 2: merged branch GEMM [B,6144]
    gemm_nt<EPI_HB><<<dim3(3 * D / GBN, Bn / GBM), 256, SMEM_GEMM>>>(
        xh, Mh, bfold, nullptr, nullptr, (void*)branch, Bn, 3 * D, D);
    // launch 3 (ncu capture slot): fused triple LayerNorm -> concat
    ln3_kernel<<<Bn, 256>>>(xh, branch, gbh, concat);
    // launch 4: h1 = relu(concat @ fw1^T + fb1)
    gemm_nt<EPI_HBR><<<dim3(D / GBN, Bn / GBM), 256, SMEM_GEMM>>>(
        concat, fw1h, fb1, nullptr, nullptr, (void*)h1, Bn, D, 3 * D);
    // launch 5: fused = h1 @ fw2^T + fb2
    gemm_nt<EPI_HB><<<dim3(D / GBN, Bn / GBM), 256, SMEM_GEMM>>>(
        h1, fw2h, fb2, nullptr, nullptr, (void*)fused, Bn, D, D);
    // launch 6: h2 = relu(fused @ ffw1^T + ffb1)
    gemm_nt<EPI_HBR><<<dim3(4 * D / GBN, Bn / GBM), 256, SMEM_GEMM>>>(
        fused, ffw1h, ffb1, nullptr, nullptr, (void*)h2, Bn, 4 * D, D);
    // launch 7: out = x + fused + (h2 @ ffw2^T + ffb2)
    gemm_nt<EPI_FINAL><<<dim3(D / GBN, Bn / GBM), 256, SMEM_GEMM>>>(
        h2, ffw2h, ffb2, x, fused, d_out, Bn, D, 4 * D);
}